// round 13
// baseline (speedup 1.0000x reference)
#include <cuda_runtime.h>
#include <cstdint>

#define B_    8
#define T_    4096
#define R_    1024
#define F_    64
#define I_    32
#define KTOT  96            // F_ + I_
#define NBLK  128           // scan blocks (8 rows of W_hh each)
#define NTHR  256

// ---------------- device scratch (no allocations allowed) ----------------
// self-validating hidden state: stored value = h + phase_offset(step), offsets
// cycle {2,6,10,14}; consumers poll until data is in the expected range.
__device__ float g_h[2][R_][B_];

__device__ __forceinline__ float phase_off(int t) {
    return 2.0f + 4.0f * (float)(t & 3);
}

// ---------------- helpers ----------------
__device__ __forceinline__ unsigned long long pack2(float a, float b) {
    unsigned long long r;
    asm("mov.b64 %0, {%1, %2};" : "=l"(r) : "f"(a), "f"(b));
    return r;
}
__device__ __forceinline__ void fma2(unsigned long long& d, unsigned long long a, unsigned long long b) {
    asm("fma.rn.f32x2 %0, %1, %2, %0;" : "+l"(d) : "l"(a), "l"(b));
}
__device__ __forceinline__ unsigned long long add2(unsigned long long a, unsigned long long b) {
    unsigned long long r;
    asm("add.rn.f32x2 %0, %1, %2;" : "=l"(r) : "l"(a), "l"(b));
    return r;
}
__device__ __forceinline__ float2 unpack2(unsigned long long v) {
    float2 f;
    asm("mov.b64 {%0, %1}, %2;" : "=f"(f.x), "=f"(f.y) : "l"(v));
    return f;
}
__device__ __forceinline__ float tanh_fast(float x) {
    float y;
    asm("tanh.approx.f32 %0, %1;" : "=f"(y) : "f"(x));
    return y;
}

template <int HALF>
__device__ __forceinline__ void reduce_round(unsigned long long* a, int lane, int d) {
    const bool hi = (lane & d) != 0;
#pragma unroll
    for (int i = 0; i < HALF; i++) {
        unsigned long long send = hi ? a[i] : a[i + HALF];
        unsigned long long keep = hi ? a[i + HALF] : a[i];
        unsigned long long recv = __shfl_xor_sync(0xffffffffu, send, d);
        a[i] = add2(keep, recv);
    }
}

// ---------------- drive GEMM (+ folded reset): out[bt][r] = X @ [Wfb|Win]^T + b ----
#define DRIVE_SMEM ((64 + 128) * 97 * 4)

__global__ __launch_bounds__(256) void drive_kernel(
    const float* __restrict__ fb, const float* __restrict__ drv,
    const float* __restrict__ Wfb, const float* __restrict__ Win,
    const float* __restrict__ bias, float* __restrict__ out)
{
    extern __shared__ float smem[];
    float (*xs)[97]  = (float (*)[97])smem;              // [64][97]
    float (*wsh)[97] = (float (*)[97])(smem + 64 * 97);  // [128][97]

    const int r0  = blockIdx.x * 128;
    const int bt0 = blockIdx.y * 64;
    const int tid = threadIdx.x;

    // folded reset (blocks y==0): buf0 = 2.0 (phase-0 data, h=0), buf1 = 0 (invalid)
    if (blockIdx.y == 0) {
        const int chunk = 2 * R_ * B_ / 8;   // 2048 floats per block
        float* p = &g_h[0][0][0];
        for (int i = tid; i < chunk; i += 256) {
            int g = blockIdx.x * chunk + i;
            p[g] = (g < R_ * B_) ? 2.0f : 0.0f;
        }
    }

    for (int idx = tid; idx < 64 * KTOT; idx += 256) {
        int row = idx / KTOT, col = idx - row * KTOT;
        float v = (col < F_) ? fb[(size_t)(bt0 + row) * F_ + col]
                             : drv[(size_t)(bt0 + row) * I_ + (col - F_)];
        xs[row][col] = v;
    }
    for (int idx = tid; idx < 128 * KTOT; idx += 256) {
        int row = idx / KTOT, col = idx - row * KTOT;
        int r = r0 + row;
        float v = (col < F_) ? Wfb[r * F_ + col] : Win[r * I_ + (col - F_)];
        wsh[row][col] = v;
    }
    __syncthreads();

    const int tx = tid & 15;
    const int ty = tid >> 4;

    float acc[4][8];
#pragma unroll
    for (int i = 0; i < 4; i++)
#pragma unroll
        for (int j = 0; j < 8; j++) acc[i][j] = 0.0f;

    for (int f = 0; f < KTOT; f++) {
        float x0 = xs[ty * 4 + 0][f];
        float x1 = xs[ty * 4 + 1][f];
        float x2 = xs[ty * 4 + 2][f];
        float x3 = xs[ty * 4 + 3][f];
        float w[8];
#pragma unroll
        for (int j = 0; j < 8; j++) w[j] = wsh[tx + 16 * j][f];
#pragma unroll
        for (int j = 0; j < 8; j++) {
            acc[0][j] = fmaf(x0, w[j], acc[0][j]);
            acc[1][j] = fmaf(x1, w[j], acc[1][j]);
            acc[2][j] = fmaf(x2, w[j], acc[2][j]);
            acc[3][j] = fmaf(x3, w[j], acc[3][j]);
        }
    }

#pragma unroll
    for (int j = 0; j < 8; j++) {
        int r = r0 + tx + 16 * j;
        float bv = bias[r];
#pragma unroll
        for (int i = 0; i < 4; i++) {
            size_t bt = (size_t)bt0 + ty * 4 + i;
            out[bt * R_ + r] = acc[i][j] + bv;
        }
    }
}

// ---------------- sequential scan: persistent, self-validating dataflow ----------
__global__ __launch_bounds__(NTHR, 1) void scan_kernel(
    const float* __restrict__ Whh, float* __restrict__ out)
{
    __shared__ float2 partials[2][8][32];   // double-buffered by t&1

    const int tid  = threadIdx.x;
    const int lane = tid & 31;
    const int warp = tid >> 5;
    const int r0   = blockIdx.x * 8;
    const int half = tid & 1;
    const int kq   = tid >> 1;

    // preload W_hh slice (dup pairs) + per-row weight sums for offset correction
    unsigned long long wd[8][8];
    float s[8];
#pragma unroll
    for (int j = 0; j < 8; j++) s[j] = 0.0f;
#pragma unroll
    for (int i = 0; i < 8; i++) {
        int k = kq + i * 128;
#pragma unroll
        for (int j = 0; j < 8; j++) {
            float w = Whh[(size_t)(r0 + j) * R_ + k];
            wd[i][j] = pack2(w, w);
            s[j] += w;
        }
    }
    unsigned long long Sd[8];
#pragma unroll
    for (int j = 0; j < 8; j++) Sd[j] = pack2(s[j], s[j]);

    const float alpha = 0.9f;
    const float onem  = 1.0f - alpha;

    size_t oi0 = 0, oi1 = 0;
    float hprev0 = 0.0f, hprev1 = 0.0f;
    float pv0 = 0.0f, pv1 = 0.0f;        // deferred out-store values
    int er = 0, eb0 = 0;
    if (warp == 0) {
        int j = lane >> 2, p = lane & 3;
        er = r0 + j; eb0 = 2 * p;
        oi0 = ((size_t)eb0 * T_) * R_ + er;
        oi1 = ((size_t)(eb0 + 1) * T_) * R_ + er;
    }

    for (int t = 0; t < T_; t++) {
        const int cur = t & 1, nxt = cur ^ 1;
        const float co = phase_off(t);        // expected phase of consumed data
        const float no = phase_off(t + 1);    // phase written for next step

        // ---- u(t) load + deferred out store: overlap with polling ----
        float u0 = 0.0f, u1 = 0.0f;
        if (warp == 0) {
            u0 = __ldcs(&out[oi0 + (size_t)t * R_]);
            u1 = __ldcs(&out[oi1 + (size_t)t * R_]);
            if (t > 0) {
                __stcg(&out[oi0 + (size_t)(t - 1) * R_], pv0);
                __stcg(&out[oi1 + (size_t)(t - 1) * R_], pv1);
            }
        }

        // ---- poll h chunks (the data IS the barrier); FMA fused on success ----
        unsigned long long acc[16];
#pragma unroll
        for (int o = 0; o < 16; o++) acc[o] = 0ull;

        const float4* hsrc = reinterpret_cast<const float4*>(&g_h[cur][0][0]);
        unsigned vm = 0;
        while (vm != 0xFFu) {
#pragma unroll
            for (int i = 0; i < 8; i++) {
                if (!((vm >> i) & 1u)) {
                    const float4* p = hsrc + ((kq + i * 128) * 2 + half);
                    float4 v;
                    asm volatile("ld.global.cg.v4.f32 {%0,%1,%2,%3}, [%4];"
                                 : "=f"(v.x), "=f"(v.y), "=f"(v.z), "=f"(v.w)
                                 : "l"(p) : "memory");
                    bool ok = (fabsf(v.x - co) <= 1.5f) & (fabsf(v.y - co) <= 1.5f) &
                              (fabsf(v.z - co) <= 1.5f) & (fabsf(v.w - co) <= 1.5f);
                    if (ok) {
                        vm |= (1u << i);
                        unsigned long long h01 = pack2(v.x, v.y);
                        unsigned long long h23 = pack2(v.z, v.w);
#pragma unroll
                        for (int j = 0; j < 8; j++) {
                            fma2(acc[j * 2 + 0], h01, wd[i][j]);
                            fma2(acc[j * 2 + 1], h23, wd[i][j]);
                        }
                    }
                }
            }
        }

        // ---- offset correction: acc -= co * S_j ----
        {
            unsigned long long negco = pack2(-co, -co);
#pragma unroll
            for (int j = 0; j < 8; j++) {
                fma2(acc[j * 2 + 0], Sd[j], negco);
                fma2(acc[j * 2 + 1], Sd[j], negco);
            }
        }

        // ---- log-halving warp reduction ----
        reduce_round<8>(acc, lane, 2);
        reduce_round<4>(acc, lane, 4);
        reduce_round<2>(acc, lane, 8);
        reduce_round<1>(acc, lane, 16);

        {
            int o = (((lane >> 1) & 1) << 3) | (((lane >> 2) & 1) << 2) |
                    (((lane >> 3) & 1) << 1) | ((lane >> 4) & 1);
            int j = o >> 1, q = o & 1;
            int p = 2 * half + q;
            partials[cur][warp][j * 4 + p] = unpack2(acc[0]);
        }
        __syncthreads();                                   // (A) the only barrier

        // ---- epilogue: warp0 tree-add + tanh + phase-offset store ----
        if (warp == 0) {
            float2 p0 = partials[cur][0][lane], p1 = partials[cur][1][lane];
            float2 p2 = partials[cur][2][lane], p3 = partials[cur][3][lane];
            float2 p4 = partials[cur][4][lane], p5 = partials[cur][5][lane];
            float2 p6 = partials[cur][6][lane], p7 = partials[cur][7][lane];
            float sx = ((p0.x + p1.x) + (p2.x + p3.x)) + ((p4.x + p5.x) + (p6.x + p7.x));
            float sy = ((p0.y + p1.y) + (p2.y + p3.y)) + ((p4.y + p5.y) + (p6.y + p7.y));

            float v0 = tanh_fast(onem * hprev0 + alpha * (u0 + sx));
            float v1 = tanh_fast(onem * hprev1 + alpha * (u1 + sy));
            // publish with next step's phase offset — store IS the flag
            __stcg(reinterpret_cast<float2*>(&g_h[nxt][er][eb0]),
                   make_float2(v0 + no, v1 + no));
            hprev0 = v0; hprev1 = v1;
            pv0 = v0; pv1 = v1;
        }
    }

    // final out store for t = T-1
    if (warp == 0) {
        __stcg(&out[oi0 + (size_t)(T_ - 1) * R_], pv0);
        __stcg(&out[oi1 + (size_t)(T_ - 1) * R_], pv1);
    }
}

// ---------------- launch ----------------
extern "C" void kernel_launch(void* const* d_in, const int* in_sizes, int n_in,
                              void* d_out, int out_size)
{
    (void)in_sizes; (void)n_in; (void)out_size;
    const float* fb   = (const float*)d_in[0];
    const float* drv  = (const float*)d_in[1];
    const float* Wfb  = (const float*)d_in[2];
    const float* Win  = (const float*)d_in[3];
    const float* Whh  = (const float*)d_in[4];
    const float* bias = (const float*)d_in[5];
    float* out = (float*)d_out;

    cudaFuncSetAttribute(drive_kernel, cudaFuncAttributeMaxDynamicSharedMemorySize, DRIVE_SMEM);

    dim3 dgrid(R_ / 128, (B_ * T_) / 64);
    drive_kernel<<<dgrid, 256, DRIVE_SMEM>>>(fb, drv, Wfb, Win, bias, out);

    scan_kernel<<<NBLK, NTHR>>>(Whh, out);
}